// round 1
// baseline (speedup 1.0000x reference)
#include <cuda_runtime.h>
#include <math.h>

// ---------------- problem constants ----------------
#define B_    32
#define S_    4096
#define HID_  5120
#define H_    16
#define DN_   128
#define DR_   64
#define DV_   128
#define QL_   1536
#define KL_   512
#define DK_   576            // 512 latent + 64 rope
#define QKV_N (QL_ + KL_ + DR_)   // 2112
#define QB_N  (H_ * (DN_ + DR_))  // 3072
#define SCALE_ 0.07216878364870323f   // 1/sqrt(192)

#define SPLITS 16
#define CHUNK  (S_ / SPLITS)  // 256
#define KROW   580            // padded K-tile row stride (conflict-free)

// ---------------- device scratch (static, no allocations) ----------------
__device__ float g_p1[8][B_][QKV_N];
__device__ float g_qkv[B_][QKV_N];
__device__ float g_qa_n[B_][QL_];
__device__ float g_latent_n[B_][KL_];
__device__ float g_kpe[B_][DR_];
__device__ float g_p2[3][B_][QB_N];
__device__ float g_q[B_][QB_N];
__device__ float g_qfinal[B_][H_][DK_];
__device__ float g_pm[B_][H_][SPLITS];
__device__ float g_pl[B_][H_][SPLITS];
__device__ float g_pctx[B_][SPLITS][H_][KL_];
__device__ float g_ctx[B_][H_][KL_];
__device__ float g_attn[B_][H_ * DV_];
__device__ float g_p3[2][B_][HID_];

// ---------------- skinny GEMM: C[32,N] = A[32,K] @ B[K,N] ----------------
// grid.x = N/64 tiles, grid.y = K splits, grid.z = heads (batched)
__global__ void __launch_bounds__(256) gemm32(
    const float* __restrict__ A, int lda, long sAh,
    const float* __restrict__ B, int ldb, long sBh,
    float* __restrict__ C, int ldc, long sCh, long cPart,
    int kchunk)
{
    __shared__ float As[32 * 36];
    __shared__ float Bs[32 * 68];

    const int n0 = blockIdx.x * 64;
    const int k0 = blockIdx.y * kchunk;
    const int h  = blockIdx.z;
    A += (long)h * sAh;
    B += (long)h * sBh + n0;
    C += (long)h * sCh + (long)blockIdx.y * cPart + n0;

    const int t  = threadIdx.x;
    const int tn = t & 15;        // 16 n-groups of 4 cols
    const int tm = t >> 4;        // 16 m-groups of 2 rows

    const int arow = t >> 3, ac4 = (t & 7) * 4;
    const int br   = t >> 4, bc4 = (t & 15) * 4;

    float4 c0 = make_float4(0.f, 0.f, 0.f, 0.f);
    float4 c1 = make_float4(0.f, 0.f, 0.f, 0.f);

    for (int k = k0; k < k0 + kchunk; k += 32) {
        float4 av  = *(const float4*)&A[(long)arow * lda + k + ac4];
        float4 bv0 = *(const float4*)&B[(long)(k + br) * ldb + bc4];
        float4 bv1 = *(const float4*)&B[(long)(k + br + 16) * ldb + bc4];
        *(float4*)&As[arow * 36 + ac4]      = av;
        *(float4*)&Bs[br * 68 + bc4]        = bv0;
        *(float4*)&Bs[(br + 16) * 68 + bc4] = bv1;
        __syncthreads();
        #pragma unroll
        for (int kk = 0; kk < 32; kk++) {
            float a0 = As[(tm * 2)     * 36 + kk];
            float a1 = As[(tm * 2 + 1) * 36 + kk];
            float4 b4 = *(float4*)&Bs[kk * 68 + tn * 4];
            c0.x += a0 * b4.x; c0.y += a0 * b4.y; c0.z += a0 * b4.z; c0.w += a0 * b4.w;
            c1.x += a1 * b4.x; c1.y += a1 * b4.y; c1.z += a1 * b4.z; c1.w += a1 * b4.w;
        }
        __syncthreads();
    }
    *(float4*)&C[(long)(tm * 2)     * ldc + tn * 4] = c0;
    *(float4*)&C[(long)(tm * 2 + 1) * ldc + tn * 4] = c1;
}

// ---------------- split-K reduce ----------------
__global__ void reduceK(const float* __restrict__ parts, float* __restrict__ out,
                        int n, int nparts, long stride)
{
    for (int i = blockIdx.x * blockDim.x + threadIdx.x; i < n; i += gridDim.x * blockDim.x) {
        float s = 0.f;
        for (int j = 0; j < nparts; j++) s += parts[(long)j * stride + i];
        out[i] = s;
    }
}

// ---------------- rmsnorm(q_a), rmsnorm(latent), rope(k_pe) ----------------
__global__ void prep_kernel(const int* __restrict__ positions,
                            const float* __restrict__ q_w,
                            const float* __restrict__ kv_w)
{
    const int b = blockIdx.x, t = threadIdx.x;
    const float* row = &g_qkv[b][0];
    __shared__ float red[256];

    // rmsnorm q_a (1536)
    float ss = 0.f;
    for (int i = t; i < QL_; i += 256) { float v = row[i]; ss += v * v; }
    red[t] = ss; __syncthreads();
    for (int o = 128; o > 0; o >>= 1) { if (t < o) red[t] += red[t + o]; __syncthreads(); }
    float r1 = rsqrtf(red[0] / (float)QL_ + 1e-6f);
    __syncthreads();
    for (int i = t; i < QL_; i += 256) g_qa_n[b][i] = row[i] * r1 * q_w[i];

    // rmsnorm latent (512)
    ss = 0.f;
    for (int i = t; i < KL_; i += 256) { float v = row[QL_ + i]; ss += v * v; }
    red[t] = ss; __syncthreads();
    for (int o = 128; o > 0; o >>= 1) { if (t < o) red[t] += red[t + o]; __syncthreads(); }
    float r2 = rsqrtf(red[0] / (float)KL_ + 1e-6f);
    __syncthreads();
    for (int i = t; i < KL_; i += 256) g_latent_n[b][i] = row[QL_ + i] * r2 * kv_w[i];

    // rope k_pe (64, interleaved)
    if (t < 32) {
        float x1 = row[QL_ + KL_ + 2 * t];
        float x2 = row[QL_ + KL_ + 2 * t + 1];
        float inv = (float)exp(-(double)(2 * t) / 64.0 * 9.210340371976184); // ln(10000)
        float fr = (float)positions[b] * inv;
        float c = cosf(fr), s = sinf(fr);
        g_kpe[b][2 * t]     = x1 * c - x2 * s;
        g_kpe[b][2 * t + 1] = x2 * c + x1 * s;
    }
}

// ---------------- rope on q_pe, write into combined query tail ----------------
__global__ void rope_q(const int* __restrict__ positions)
{
    const int b = blockIdx.x, t = threadIdx.x;
    const float pos = (float)positions[b];
    for (int idx = t; idx < H_ * 32; idx += 256) {
        int h = idx >> 5, i = idx & 31;
        float x1 = g_q[b][h * 192 + 128 + 2 * i];
        float x2 = g_q[b][h * 192 + 128 + 2 * i + 1];
        float inv = (float)exp(-(double)(2 * i) / 64.0 * 9.210340371976184);
        float fr = pos * inv;
        float c = cosf(fr), s = sinf(fr);
        g_qfinal[b][h][512 + 2 * i]     = x1 * c - x2 * s;
        g_qfinal[b][h][512 + 2 * i + 1] = x2 * c + x1 * s;
    }
}

// ---------------- flash-decode attention (split over S) ----------------
// grid: (SPLITS, B), 256 threads. Q[16,576] and K-tiles[16,576] in smem.
// Thread t: head hg = t>>4, group lg = t&15. One score per thread per tile;
// ctx accumulator 16h x 512c kept in registers (32 floats/thread).
__global__ void __launch_bounds__(256) attn_kernel(
    const float* __restrict__ cache_l,
    const float* __restrict__ cache_r)
{
    extern __shared__ float smem[];
    float* sQ = smem;                 // 16*576
    float* sK = sQ + 16 * 576;        // 16*KROW
    float* sP = sK + 16 * KROW;       // 256
    float* sM = sP + 256;             // 16
    float* sL = sM + 16;              // 16
    float* sC = sL + 16;              // 16

    const int split = blockIdx.x, b = blockIdx.y;
    const int t = threadIdx.x;
    const int hg = t >> 4, lg = t & 15;

    // load Q (all 16 heads, 576 dims)
    for (int i = t; i < 16 * 144; i += 256)
        ((float4*)sQ)[i] = ((const float4*)&g_qfinal[b][0][0])[i];
    if (t < 16) { sM[t] = -1e30f; sL[t] = 0.f; }

    float4 acc[8];
    #pragma unroll
    for (int j = 0; j < 8; j++) acc[j] = make_float4(0.f, 0.f, 0.f, 0.f);

    const int s0 = split * CHUNK;
    for (int tile = 0; tile < CHUNK / 16; tile++) {
        const int sbase = s0 + tile * 16;
        __syncthreads();   // protects sK/sP reuse and first-iter Q/M/L init

        // stage K tile: 16 rows x 576 floats (144 float4/row)
        for (int i = t; i < 16 * 144; i += 256) {
            int r = i / 144, c4 = i % 144;
            int s = sbase + r;
            float4 v;
            if (s == S_ - 1) {  // cache override with fresh token
                if (c4 < 128) v = ((const float4*)&g_latent_n[b][0])[c4];
                else          v = ((const float4*)&g_kpe[b][0])[c4 - 128];
            } else {
                if (c4 < 128) v = ((const float4*)cache_l)[((long)b * S_ + s) * 128 + c4];
                else          v = ((const float4*)cache_r)[((long)b * S_ + s) * 16 + (c4 - 128)];
            }
            *(float4*)&sK[r * KROW + c4 * 4] = v;
        }
        __syncthreads();

        // scores: one (h,s) dot of length 576 per thread
        float sc = 0.f;
        const float* qp = &sQ[hg * 576];
        const float* kp = &sK[lg * KROW];
        #pragma unroll 8
        for (int d4 = 0; d4 < 144; d4++) {
            float4 q4 = ((const float4*)qp)[d4];
            float4 k4 = ((const float4*)kp)[d4];
            sc += q4.x * k4.x + q4.y * k4.y + q4.z * k4.z + q4.w * k4.w;
        }
        sc *= SCALE_;

        // online softmax over the 16-lane group sharing this head
        float mt = sc;
        #pragma unroll
        for (int o = 8; o; o >>= 1) mt = fmaxf(mt, __shfl_xor_sync(0xffffffffu, mt, o));
        float m_old = sM[hg];
        float m_new = fmaxf(m_old, mt);
        float p = expf(sc - m_new);
        float ps = p;
        #pragma unroll
        for (int o = 8; o; o >>= 1) ps += __shfl_xor_sync(0xffffffffu, ps, o);
        sP[hg * 16 + lg] = p;
        if (lg == 0) {
            float corr = expf(m_old - m_new);
            sC[hg] = corr;
            sM[hg] = m_new;
            sL[hg] = sL[hg] * corr + ps;
        }
        __syncthreads();

        // ctx accumulate: acc[h][c] = acc*corr + sum_s P[h][s] * V[s][c]
        float corr = sC[hg];
        #pragma unroll
        for (int j = 0; j < 8; j++) {
            acc[j].x *= corr; acc[j].y *= corr; acc[j].z *= corr; acc[j].w *= corr;
        }
        #pragma unroll 4
        for (int ssi = 0; ssi < 16; ssi++) {
            float pp = sP[hg * 16 + ssi];
            const float* vp = &sK[ssi * KROW];
            #pragma unroll
            for (int j = 0; j < 8; j++) {
                float4 v4 = *(const float4*)&vp[(lg + 16 * j) * 4];
                acc[j].x += pp * v4.x; acc[j].y += pp * v4.y;
                acc[j].z += pp * v4.z; acc[j].w += pp * v4.w;
            }
        }
    }

    // write partials
    float* outp = &g_pctx[b][split][hg][0];
    #pragma unroll
    for (int j = 0; j < 8; j++)
        *(float4*)&outp[(lg + 16 * j) * 4] = acc[j];
    if (t < 16) {
        g_pm[b][t][split] = sM[t];
        g_pl[b][t][split] = sL[t];
    }
}

// ---------------- combine split partials (deterministic) ----------------
__global__ void attn_reduce()
{
    const int h = blockIdx.x, b = blockIdx.y;
    const int t = threadIdx.x;  // 128 threads, float4 over 512 cols
    __shared__ float se[SPLITS];
    __shared__ float s_inv;
    if (t == 0) {
        float M = -1e30f;
        for (int i = 0; i < SPLITS; i++) M = fmaxf(M, g_pm[b][h][i]);
        float L = 0.f;
        for (int i = 0; i < SPLITS; i++) {
            float e = expf(g_pm[b][h][i] - M);
            se[i] = e;
            L += g_pl[b][h][i] * e;
        }
        s_inv = 1.0f / L;
    }
    __syncthreads();
    float4 o = make_float4(0.f, 0.f, 0.f, 0.f);
    for (int i = 0; i < SPLITS; i++) {
        float e = se[i];
        float4 v = ((const float4*)&g_pctx[b][i][h][0])[t];
        o.x += e * v.x; o.y += e * v.y; o.z += e * v.z; o.w += e * v.w;
    }
    float inv = s_inv;
    o.x *= inv; o.y *= inv; o.z *= inv; o.w *= inv;
    ((float4*)&g_ctx[b][h][0])[t] = o;
}

// ---------------- host launcher ----------------
extern "C" void kernel_launch(void* const* d_in, const int* in_sizes, int n_in,
                              void* d_out, int out_size)
{
    (void)in_sizes; (void)n_in; (void)out_size;
    const float* hidden    = (const float*)d_in[0];
    const int*   positions = (const int*)  d_in[1];
    const float* cache_l   = (const float*)d_in[2];
    const float* cache_r   = (const float*)d_in[3];
    const float* w_qkv_a   = (const float*)d_in[4];
    const float* q_norm_w  = (const float*)d_in[5];
    const float* w_q_b     = (const float*)d_in[6];
    const float* kv_norm_w = (const float*)d_in[7];
    const float* w_kc      = (const float*)d_in[8];
    const float* w_vc      = (const float*)d_in[9];
    const float* w_o       = (const float*)d_in[10];
    float* out = (float*)d_out;

    float *p1, *qkv, *qa_n, *p2, *q, *qf, *ctx, *attnb, *p3;
    cudaGetSymbolAddress((void**)&p1,    g_p1);
    cudaGetSymbolAddress((void**)&qkv,   g_qkv);
    cudaGetSymbolAddress((void**)&qa_n,  g_qa_n);
    cudaGetSymbolAddress((void**)&p2,    g_p2);
    cudaGetSymbolAddress((void**)&q,     g_q);
    cudaGetSymbolAddress((void**)&qf,    g_qfinal);
    cudaGetSymbolAddress((void**)&ctx,   g_ctx);
    cudaGetSymbolAddress((void**)&attnb, g_attn);
    cudaGetSymbolAddress((void**)&p3,    g_p3);

    const int ATTN_SMEM = (16 * 576 + 16 * KROW + 256 + 48) * 4;  // 75200 B
    cudaFuncSetAttribute(attn_kernel, cudaFuncAttributeMaxDynamicSharedMemorySize, ATTN_SMEM);

    // 1) qkv = hidden @ w_qkv_a   (split-K x8)
    gemm32<<<dim3(QKV_N / 64, 8, 1), 256>>>(hidden, HID_, 0, w_qkv_a, QKV_N, 0,
                                            p1, QKV_N, 0, 32L * QKV_N, HID_ / 8);
    reduceK<<<264, 256>>>(p1, qkv, B_ * QKV_N, 8, 32L * QKV_N);

    // 2) rmsnorms + rope(k_pe)
    prep_kernel<<<B_, 256>>>(positions, q_norm_w, kv_norm_w);

    // 3) q = rmsnorm(q_a) @ w_q_b  (split-K x3)
    gemm32<<<dim3(QB_N / 64, 3, 1), 256>>>(qa_n, QL_, 0, w_q_b, QB_N, 0,
                                           p2, QB_N, 0, 32L * QB_N, QL_ / 3);
    reduceK<<<264, 256>>>(p2, q, B_ * QB_N, 3, 32L * QB_N);

    // 4) rope(q_pe) -> qfinal[...,512:576]
    rope_q<<<B_, 256>>>(positions);

    // 5) q_abs = q_nope @ w_kc[h] -> qfinal[...,0:512]  (batched over heads)
    gemm32<<<dim3(KL_ / 64, 1, H_), 256>>>(q, QB_N, 192, w_kc, KL_, (long)DN_ * KL_,
                                           qf, H_ * DK_, DK_, 0, DN_);

    // 6) flash-decode attention
    attn_kernel<<<dim3(SPLITS, B_), 256, ATTN_SMEM>>>(cache_l, cache_r);
    attn_reduce<<<dim3(H_, B_), 128>>>();

    // 7) per-head value projection: attn = ctx @ w_vc[h]
    gemm32<<<dim3(DV_ / 64, 1, H_), 256>>>(ctx, H_ * KL_, KL_, w_vc, DV_, (long)KL_ * DV_,
                                           attnb, H_ * DV_, DV_, 0, KL_);

    // 8) out = attn @ w_o   (split-K x2)
    gemm32<<<dim3(HID_ / 64, 2, 1), 256>>>(attnb, H_ * DV_, 0, w_o, HID_, 0,
                                           p3, HID_, 0, 32L * HID_, (H_ * DV_) / 2);
    reduceK<<<264, 256>>>(p3, out, B_ * HID_, 2, 32L * HID_);
}